// round 17
// baseline (speedup 1.0000x reference)
#include <cuda_runtime.h>
#include <cuda_bf16.h>
#include <math.h>
#include <cstdint>

// Problem constants
#define BATCH   1024
#define NPART   32
#define ROWS    32768
#define DOBS    17
#define DACT    6
#define HID     256
#define NSTEPS  5
#define LRC     0.05f
#define A_TOTAL (ROWS*DACT)

#define MTI         64             // M rows per GEMM CTA
#define TILES       (ROWS/MTI)     // 512 per net
#define KC          32             // K per smem chunk
#define NCHUNK      (HID/KC)       // 8
#define SSTRB       80             // smem row stride in BYTES (32 bf16 + 8 pad)

// ---------------- device scratch (allocation-free rule) ---------------------
__device__ float d_aproj[2][ROWS*HID];
__device__ __nv_bfloat16 d_w2h [2][HID*HID];   // W2 native [k_in][c_out] -> bwd B
__device__ __nv_bfloat16 d_w2l [2][HID*HID];
__device__ __nv_bfloat16 d_w2th[2][HID*HID];   // W2 transposed [n][k]    -> fwd B
__device__ __nv_bfloat16 d_w2tl[2][HID*HID];
__device__ __nv_bfloat16 d_w3h [2][HID];
__device__ __nv_bfloat16 d_w3l [2][HID];
__device__ float d_qv [2][ROWS];
__device__ float d_sv [2][ROWS*DACT];
__device__ float d_av [A_TOTAL];
__device__ float d_lp [ROWS];

// ---------------- helpers ----------------------------------------------------
__device__ __forceinline__ uint32_t smem_u32(const void* p) {
    uint32_t a;
    asm("{ .reg .u64 t; cvta.to.shared.u64 t, %1; cvt.u32.u64 %0, t; }" : "=r"(a) : "l"(p));
    return a;
}

__device__ __forceinline__ void split_bf16(float x, __nv_bfloat16& h, __nv_bfloat16& l) {
    h = __float2bfloat16_rn(x);
    l = __float2bfloat16_rn(x - __bfloat162float(h));
}

__device__ __forceinline__ void mma_bf16(float* c,
    uint32_t a0, uint32_t a1, uint32_t a2, uint32_t a3,
    uint32_t b0, uint32_t b1) {
    asm volatile(
        "mma.sync.aligned.m16n8k16.row.col.f32.bf16.bf16.f32 "
        "{%0,%1,%2,%3}, {%4,%5,%6,%7}, {%8,%9}, {%0,%1,%2,%3};"
        : "+f"(c[0]), "+f"(c[1]), "+f"(c[2]), "+f"(c[3])
        : "r"(a0), "r"(a1), "r"(a2), "r"(a3), "r"(b0), "r"(b1));
}

#define LDSM4(R0,R1,R2,R3,ADDR) \
    asm volatile("ldmatrix.sync.aligned.m8n8.x4.shared.b16 {%0,%1,%2,%3}, [%4];" \
        : "=r"(R0), "=r"(R1), "=r"(R2), "=r"(R3) : "r"(ADDR))

#define CP_ASYNC16(dst, src) \
    asm volatile("cp.async.cg.shared.global [%0], [%1], 16;" :: "r"(dst), "l"(src))
#define CP_COMMIT() asm volatile("cp.async.commit_group;" ::: "memory")
#define CP_WAIT0()  asm volatile("cp.async.wait_group 0;" ::: "memory")
#define CP_WAIT1()  asm volatile("cp.async.wait_group 1;" ::: "memory")

// ---------------- smem layout (bytes) ----------------------------------------
#define OFF_AH   0                         // 64*80      = 5120
#define OFF_AL   5120                      // 5120
#define OFF_BH0  10240                     // 256*80     = 20480
#define OFF_BL0  30720
#define OFF_BH1  51200
#define OFF_BL1  71680
#define BSTAGE   40960                     // OFF_BH1 - OFF_BH0
#define OFF_W1A  92160                     // 6*256*4    = 6144
#define OFF_ASM  98304                     // 64*6*4     = 1536
#define OFF_B2   99840                     // 1024
#define OFF_W3   100864                    // 1024
#define OFF_W3H  101888                    // 512 (bf16)
#define OFF_W3L  102400                    // 512
#define OFF_QP   102912                    // 256
#define OFF_SP   103168                    // 64*6*4 = 1536
#define OFF_H1M  104704                    // 64*32 bits = 2048
#define OFF_H2M  106752                    // 2048
#define SMEM_TOTAL 108800

// ---------------- init -------------------------------------------------------
__global__ void init_kernel(const float* __restrict__ a0, float* __restrict__ a,
                            float* __restrict__ lp) {
    int idx = blockIdx.x * blockDim.x + threadIdx.x;
    if (idx < A_TOTAL) a[idx] = a0[idx];
    if (idx < ROWS)    lp[idx] = 0.f;
}

// ---------------- weight prep: bf16 hi/lo splits + W2 transpose --------------
__global__ void prep_kernel(const float* __restrict__ W2a, const float* __restrict__ W2b,
                            const float* __restrict__ W3a, const float* __restrict__ W3b) {
    int idx = blockIdx.x * blockDim.x + threadIdx.x; // 131072
    int net = idx >> 16;
    int e   = idx & 65535;
    const float* W2 = net ? W2b : W2a;
    __nv_bfloat16 hi, lo;
    split_bf16(W2[e], hi, lo);
    int k = e >> 8, n = e & 255;
    d_w2h[net][e] = hi;            d_w2l[net][e] = lo;           // [k][n]
    d_w2th[net][n*HID + k] = hi;   d_w2tl[net][n*HID + k] = lo;  // [n][k]
    if (idx < 2*HID) {
        int nt = idx >> 8, c = idx & 255;
        const float* W3 = nt ? W3b : W3a;
        __nv_bfloat16 h3, l3;
        split_bf16(W3[c], h3, l3);
        d_w3h[nt][c] = h3;  d_w3l[nt][c] = l3;
    }
}

// ---------------- obs projection (conflict-free): both nets ------------------
__global__ __launch_bounds__(256)
void obsproj_kernel(const float* __restrict__ obs,
                    const float* __restrict__ W1a_, const float* __restrict__ W1b_,
                    const float* __restrict__ b1a, const float* __restrict__ b1b,
                    float* __restrict__ aprojB) {
    __shared__ float w1o[DOBS*HID];
    __shared__ float obs_s[32*DOBS];
    __shared__ float b1s[HID];
    const int tid = threadIdx.x;
    const int net = blockIdx.x >> 10;
    const int r0  = (blockIdx.x & 1023) * 32;
    const float* W1 = net ? W1b_ : W1a_;
    const float* b1 = net ? b1b  : b1a;
    float* aproj = aprojB + (size_t)net * ROWS * HID;

    for (int i = tid; i < DOBS*HID; i += 256) w1o[i] = W1[i];
    for (int i = tid; i < 32*DOBS; i += 256)  obs_s[i] = obs[r0*DOBS + i];
    b1s[tid] = b1[tid];
    __syncthreads();

    const int warp = tid >> 5, lane = tid & 31;
#pragma unroll
    for (int rr = 0; rr < 4; rr++) {
        const int row = warp*4 + rr;
        float ob[DOBS];
#pragma unroll
        for (int d = 0; d < DOBS; d++) ob[d] = obs_s[row*DOBS + d];
        float* dst = aproj + (size_t)(r0 + row)*HID;
#pragma unroll
        for (int k = 0; k < 8; k++) {
            const int c = lane + k*32;
            float acc = b1s[c];
#pragma unroll
            for (int d = 0; d < DOBS; d++) acc = fmaf(ob[d], w1o[d*HID + c], acc);
            dst[c] = acc;
        }
    }
}

// ---------------- fused fwd+bwd GEMM step (mma.sync bf16x3) ------------------
// Phase 1 (fwd): A = h1 = relu(aproj + a@W1a) built on the fly; D = h1 @ W2.
//   Epilogue: q = relu(D+b2).W3 + b3 ; h1/h2 relu masks bit-packed in smem.
// Phase 2 (bwd): A = g2 = mask2 ? W3 : 0 ; D = g2 @ W2^T.
//   Epilogue: s = ((h1>0).*D) @ W1a^T.
__global__ void __launch_bounds__(256, 2) gemm_step_mma(
    const float* __restrict__ aprojB, const float* __restrict__ a,
    const float* __restrict__ W1a_, const float* __restrict__ W1b_,
    const __nv_bfloat16* __restrict__ FhB, const __nv_bfloat16* __restrict__ FlB,
    const __nv_bfloat16* __restrict__ GhB, const __nv_bfloat16* __restrict__ GlB,
    const float* __restrict__ b2a, const float* __restrict__ b2b,
    const float* __restrict__ W3a_, const float* __restrict__ W3b_,
    const float* __restrict__ b3a, const float* __restrict__ b3b,
    const __nv_bfloat16* __restrict__ w3hB, const __nv_bfloat16* __restrict__ w3lB,
    float* __restrict__ qoutB, float* __restrict__ soutB)
{
    extern __shared__ char smem[];
    const uint32_t sb = smem_u32(smem);
    float* w1a  = (float*)(smem + OFF_W1A);
    float* a_sm = (float*)(smem + OFF_ASM);
    float* b2s  = (float*)(smem + OFF_B2);
    float* w3s  = (float*)(smem + OFF_W3);
    __nv_bfloat16* w3hs = (__nv_bfloat16*)(smem + OFF_W3H);
    __nv_bfloat16* w3ls = (__nv_bfloat16*)(smem + OFF_W3L);
    float* qp   = (float*)(smem + OFF_QP);
    float* sp   = (float*)(smem + OFF_SP);
    unsigned char* h1mb = (unsigned char*)(smem + OFF_H1M);
    unsigned char* h2mb = (unsigned char*)(smem + OFF_H2M);

    const int tid = threadIdx.x;
    const int net = blockIdx.x >> 9;
    const int M0  = (blockIdx.x & 511) * MTI;
    const size_t PLANE = (size_t)ROWS * HID;
    const float* aproj = aprojB + net*PLANE;
    const float* W1 = net ? W1b_ : W1a_;
    const __nv_bfloat16* Fh = FhB + (size_t)net*HID*HID;
    const __nv_bfloat16* Fl = FlB + (size_t)net*HID*HID;
    const __nv_bfloat16* Gh = GhB + (size_t)net*HID*HID;
    const __nv_bfloat16* Gl = GlB + (size_t)net*HID*HID;
    const float* b2 = net ? b2b : b2a;
    const float* W3 = net ? W3b_ : W3a_;
    const float* b3 = net ? b3b : b3a;

    for (int i = tid; i < 6*HID; i += 256) w1a[i] = W1[DOBS*HID + i];
    for (int i = tid; i < MTI*DACT; i += 256) a_sm[i] = a[(size_t)M0*DACT + i];
    b2s[tid] = b2[tid];
    w3s[tid] = W3[tid];
    w3hs[tid] = w3hB[net*HID + tid];
    w3ls[tid] = w3lB[net*HID + tid];
    if (tid < MTI) qp[tid] = 0.f;
    for (int i = tid; i < MTI*DACT; i += 256) sp[i] = 0.f;

    const int arow = tid >> 2;
    const int cg   = (tid & 3) * 8;       // 8 cols per thread per chunk
    const int lane = tid & 31, warp = tid >> 5;
    const int wm = warp & 1, wn = warp >> 1;
    const int g = lane >> 2, t4 = lane & 3;
    __syncthreads();

    float av[DACT];
#pragma unroll
    for (int j = 0; j < DACT; j++) av[j] = a_sm[arow*DACT + j];

    float acc[2][8][4];
#pragma unroll
    for (int i = 0; i < 2; i++)
#pragma unroll
        for (int j = 0; j < 8; j++)
#pragma unroll
            for (int k = 0; k < 4; k++) acc[i][j][k] = 0.f;

    const float* aprow = aproj + (size_t)(M0 + arow)*HID + cg;
    const uint32_t a_st_h = sb + OFF_AH + arow*SSTRB + cg*2;
    const uint32_t a_st_l = sb + OFF_AL + arow*SSTRB + cg*2;
    // ldmatrix lane addresses
    const uint32_t a_lm_h = sb + OFF_AH + (wm*32 + (lane & 15))*SSTRB + (lane >> 4)*16;
    const uint32_t a_lm_l = a_lm_h + (OFF_AL - OFF_AH);
    const uint32_t b_lmo  = (wn*64 + ((lane >> 4) << 3) + (lane & 7))*SSTRB + (lane & 8)*2;
    const int mbidx = arow*32 + (tid & 3);   // mask byte base (per chunk: + c*4)

    // ======================= PHASE 1: forward =======================
    {
        const __nv_bfloat16* bhrow = Fh + (size_t)tid*HID;
        const __nv_bfloat16* blrow = Fl + (size_t)tid*HID;

        float4 pr0 = *(const float4*)(aprow + 0);
        float4 pr1 = *(const float4*)(aprow + 4);

        {   // prologue: B[0]
            const uint32_t bh_dst = sb + OFF_BH0 + tid*SSTRB;
#pragma unroll
            for (int kk = 0; kk < 4; kk++) {
                CP_ASYNC16(bh_dst + kk*16, bhrow + kk*8);
                CP_ASYNC16(bh_dst + (OFF_BL0-OFF_BH0) + kk*16, blrow + kk*8);
            }
            CP_COMMIT();
        }

        for (int c = 0; c < NCHUNK; c++) {
            const int k0 = c * KC;
            __syncthreads();
            if (c + 1 < NCHUNK) {
                const uint32_t bh_dst = sb + OFF_BH0 + ((c+1)&1)*BSTAGE + tid*SSTRB;
#pragma unroll
                for (int kk = 0; kk < 4; kk++) {
                    CP_ASYNC16(bh_dst + kk*16, bhrow + k0 + KC + kk*8);
                    CP_ASYNC16(bh_dst + (OFF_BL0-OFF_BH0) + kk*16, blrow + k0 + KC + kk*8);
                }
                CP_COMMIT();
            }
            // A build: h1 + h1 mask bits (smem)
            {
                float pre[8] = {pr0.x,pr0.y,pr0.z,pr0.w, pr1.x,pr1.y,pr1.z,pr1.w};
                __nv_bfloat16 hh[8], ll[8];
                uint32_t m8 = 0u;
#pragma unroll
                for (int e = 0; e < 8; e++) {
                    const int col = k0 + cg + e;
                    float v = pre[e];
#pragma unroll
                    for (int j = 0; j < DACT; j++) v = fmaf(av[j], w1a[j*HID + col], v);
                    uint32_t pos = v > 0.f ? 1u : 0u;
                    v = pos ? v : 0.f;
                    split_bf16(v, hh[e], ll[e]);
                    m8 |= pos << e;
                }
                h1mb[mbidx + c*4] = (unsigned char)m8;
                *(uint4*)(smem + (a_st_h - sb)) = *(uint4*)hh;
                *(uint4*)(smem + (a_st_l - sb)) = *(uint4*)ll;
            }
            if (c + 1 < NCHUNK) {
                pr0 = *(const float4*)(aprow + (c+1)*KC + 0);
                pr1 = *(const float4*)(aprow + (c+1)*KC + 4);
            }
            if (c + 1 < NCHUNK) { CP_WAIT1(); } else { CP_WAIT0(); }
            __syncthreads();
            const uint32_t bbase = sb + OFF_BH0 + (c&1)*BSTAGE + b_lmo;
#pragma unroll
            for (int ks = 0; ks < 2; ks++) {
                uint32_t ah[2][4], al[2][4];
                LDSM4(ah[0][0],ah[0][1],ah[0][2],ah[0][3], a_lm_h + ks*32);
                LDSM4(ah[1][0],ah[1][1],ah[1][2],ah[1][3], a_lm_h + 16*SSTRB + ks*32);
                LDSM4(al[0][0],al[0][1],al[0][2],al[0][3], a_lm_l + ks*32);
                LDSM4(al[1][0],al[1][1],al[1][2],al[1][3], a_lm_l + 16*SSTRB + ks*32);
#pragma unroll
                for (int np = 0; np < 4; np++) {
                    uint32_t bh0,bh1,bh2,bh3, bl0,bl1,bl2,bl3;
                    const uint32_t baddr = bbase + np*16*SSTRB + ks*32;
                    LDSM4(bh0,bh1,bh2,bh3, baddr);
                    LDSM4(bl0,bl1,bl2,bl3, baddr + (OFF_BL0-OFF_BH0));
#pragma unroll
                    for (int mt = 0; mt < 2; mt++) {
                        mma_bf16(acc[mt][2*np],   ah[mt][0],ah[mt][1],ah[mt][2],ah[mt][3], bh0, bh1);
                        mma_bf16(acc[mt][2*np],   ah[mt][0],ah[mt][1],ah[mt][2],ah[mt][3], bl0, bl1);
                        mma_bf16(acc[mt][2*np],   al[mt][0],al[mt][1],al[mt][2],al[mt][3], bh0, bh1);
                        mma_bf16(acc[mt][2*np+1], ah[mt][0],ah[mt][1],ah[mt][2],ah[mt][3], bh2, bh3);
                        mma_bf16(acc[mt][2*np+1], ah[mt][0],ah[mt][1],ah[mt][2],ah[mt][3], bl2, bl3);
                        mma_bf16(acc[mt][2*np+1], al[mt][0],al[mt][1],al[mt][2],al[mt][3], bh2, bh3);
                    }
                }
            }
        }
        // fwd epilogue: q + packed h2 masks
#pragma unroll
        for (int mt = 0; mt < 2; mt++) {
            int rA = wm*32 + mt*16 + g;
            int rB = rA + 8;
            float sA = 0.f, sB = 0.f;
#pragma unroll
            for (int nt = 0; nt < 8; nt++) {
                int col0 = wn*64 + nt*8 + t4*2;
                float vA0 = acc[mt][nt][0] + b2s[col0];
                float vA1 = acc[mt][nt][1] + b2s[col0+1];
                float vB0 = acc[mt][nt][2] + b2s[col0];
                float vB1 = acc[mt][nt][3] + b2s[col0+1];
                uint32_t pA0 = vA0 > 0.f, pA1 = vA1 > 0.f;
                uint32_t pB0 = vB0 > 0.f, pB1 = vB1 > 0.f;
                uint32_t bA = (pA0 | (pA1 << 1)) << (t4*2);
                uint32_t bB = (pB0 | (pB1 << 1)) << (t4*2);
                bA |= __shfl_xor_sync(0xffffffffu, bA, 1);
                bA |= __shfl_xor_sync(0xffffffffu, bA, 2);
                bB |= __shfl_xor_sync(0xffffffffu, bB, 1);
                bB |= __shfl_xor_sync(0xffffffffu, bB, 2);
                if (t4 == 0) {
                    h2mb[rA*32 + wn*8 + nt] = (unsigned char)bA;
                    h2mb[rB*32 + wn*8 + nt] = (unsigned char)bB;
                }
                vA0 = pA0 ? vA0 : 0.f;  vA1 = pA1 ? vA1 : 0.f;
                vB0 = pB0 ? vB0 : 0.f;  vB1 = pB1 ? vB1 : 0.f;
                sA = fmaf(vA0, w3s[col0], fmaf(vA1, w3s[col0+1], sA));
                sB = fmaf(vB0, w3s[col0], fmaf(vB1, w3s[col0+1], sB));
            }
            sA += __shfl_xor_sync(0xffffffffu, sA, 1);
            sA += __shfl_xor_sync(0xffffffffu, sA, 2);
            sB += __shfl_xor_sync(0xffffffffu, sB, 1);
            sB += __shfl_xor_sync(0xffffffffu, sB, 2);
            if (t4 == 0) {
                atomicAdd(&qp[rA], sA);
                atomicAdd(&qp[rB], sB);
            }
        }
    }
    __syncthreads();   // masks + qp complete
    if (tid < MTI) qoutB[net*ROWS + M0 + tid] = qp[tid] + b3[0];

    // ======================= PHASE 2: backward ======================
    {
#pragma unroll
        for (int i = 0; i < 2; i++)
#pragma unroll
            for (int j = 0; j < 8; j++)
#pragma unroll
                for (int k = 0; k < 4; k++) acc[i][j][k] = 0.f;

        const __nv_bfloat16* bhrow = Gh + (size_t)tid*HID;
        const __nv_bfloat16* blrow = Gl + (size_t)tid*HID;

        {   // prologue: B[0]
            const uint32_t bh_dst = sb + OFF_BH0 + tid*SSTRB;
#pragma unroll
            for (int kk = 0; kk < 4; kk++) {
                CP_ASYNC16(bh_dst + kk*16, bhrow + kk*8);
                CP_ASYNC16(bh_dst + (OFF_BL0-OFF_BH0) + kk*16, blrow + kk*8);
            }
            CP_COMMIT();
        }

        for (int c = 0; c < NCHUNK; c++) {
            const int k0 = c * KC;
            __syncthreads();
            if (c + 1 < NCHUNK) {
                const uint32_t bh_dst = sb + OFF_BH0 + ((c+1)&1)*BSTAGE + tid*SSTRB;
#pragma unroll
                for (int kk = 0; kk < 4; kk++) {
                    CP_ASYNC16(bh_dst + kk*16, bhrow + k0 + KC + kk*8);
                    CP_ASYNC16(bh_dst + (OFF_BL0-OFF_BH0) + kk*16, blrow + k0 + KC + kk*8);
                }
                CP_COMMIT();
            }
            // A build: g2 = mask2 ? W3 : 0 (mask bits from smem)
            {
                uint32_t m8 = h2mb[mbidx + c*4];
                __nv_bfloat16 hh[8], ll[8];
                const __nv_bfloat16 z = __float2bfloat16_rn(0.f);
#pragma unroll
                for (int e = 0; e < 8; e++) {
                    const int col = k0 + cg + e;
                    bool on = (m8 >> e) & 1u;
                    hh[e] = on ? w3hs[col] : z;
                    ll[e] = on ? w3ls[col] : z;
                }
                *(uint4*)(smem + (a_st_h - sb)) = *(uint4*)hh;
                *(uint4*)(smem + (a_st_l - sb)) = *(uint4*)ll;
            }
            if (c + 1 < NCHUNK) { CP_WAIT1(); } else { CP_WAIT0(); }
            __syncthreads();
            const uint32_t bbase = sb + OFF_BH0 + (c&1)*BSTAGE + b_lmo;
#pragma unroll
            for (int ks = 0; ks < 2; ks++) {
                uint32_t ah[2][4], al[2][4];
                LDSM4(ah[0][0],ah[0][1],ah[0][2],ah[0][3], a_lm_h + ks*32);
                LDSM4(ah[1][0],ah[1][1],ah[1][2],ah[1][3], a_lm_h + 16*SSTRB + ks*32);
                LDSM4(al[0][0],al[0][1],al[0][2],al[0][3], a_lm_l + ks*32);
                LDSM4(al[1][0],al[1][1],al[1][2],al[1][3], a_lm_l + 16*SSTRB + ks*32);
#pragma unroll
                for (int np = 0; np < 4; np++) {
                    uint32_t bh0,bh1,bh2,bh3, bl0,bl1,bl2,bl3;
                    const uint32_t baddr = bbase + np*16*SSTRB + ks*32;
                    LDSM4(bh0,bh1,bh2,bh3, baddr);
                    LDSM4(bl0,bl1,bl2,bl3, baddr + (OFF_BL0-OFF_BH0));
#pragma unroll
                    for (int mt = 0; mt < 2; mt++) {
                        mma_bf16(acc[mt][2*np],   ah[mt][0],ah[mt][1],ah[mt][2],ah[mt][3], bh0, bh1);
                        mma_bf16(acc[mt][2*np],   ah[mt][0],ah[mt][1],ah[mt][2],ah[mt][3], bl0, bl1);
                        mma_bf16(acc[mt][2*np],   al[mt][0],al[mt][1],al[mt][2],al[mt][3], bh0, bh1);
                        mma_bf16(acc[mt][2*np+1], ah[mt][0],ah[mt][1],ah[mt][2],ah[mt][3], bh2, bh3);
                        mma_bf16(acc[mt][2*np+1], ah[mt][0],ah[mt][1],ah[mt][2],ah[mt][3], bl2, bl3);
                        mma_bf16(acc[mt][2*np+1], al[mt][0],al[mt][1],al[mt][2],al[mt][3], bh2, bh3);
                    }
                }
            }
        }
        // bwd epilogue: s = ((h1>0).*D) @ W1a^T
#pragma unroll
        for (int mt = 0; mt < 2; mt++) {
            int rA = wm*32 + mt*16 + g;
            int rB = rA + 8;
            float saA[DACT], saB[DACT];
#pragma unroll
            for (int j = 0; j < DACT; j++) { saA[j] = 0.f; saB[j] = 0.f; }
#pragma unroll
            for (int nt = 0; nt < 8; nt++) {
                int col0 = wn*64 + nt*8 + t4*2;
                uint32_t mA = h1mb[rA*32 + wn*8 + nt];
                uint32_t mB = h1mb[rB*32 + wn*8 + nt];
                float gA0 = ((mA >> (t4*2)) & 1u)     ? acc[mt][nt][0] : 0.f;
                float gA1 = ((mA >> (t4*2 + 1)) & 1u) ? acc[mt][nt][1] : 0.f;
                float gB0 = ((mB >> (t4*2)) & 1u)     ? acc[mt][nt][2] : 0.f;
                float gB1 = ((mB >> (t4*2 + 1)) & 1u) ? acc[mt][nt][3] : 0.f;
#pragma unroll
                for (int j = 0; j < DACT; j++) {
                    float w0 = w1a[j*HID + col0];
                    float w1v = w1a[j*HID + col0 + 1];
                    saA[j] = fmaf(gA0, w0, fmaf(gA1, w1v, saA[j]));
                    saB[j] = fmaf(gB0, w0, fmaf(gB1, w1v, saB[j]));
                }
            }
#pragma unroll
            for (int j = 0; j < DACT; j++) {
                saA[j] += __shfl_xor_sync(0xffffffffu, saA[j], 1);
                saA[j] += __shfl_xor_sync(0xffffffffu, saA[j], 2);
                saB[j] += __shfl_xor_sync(0xffffffffu, saB[j], 1);
                saB[j] += __shfl_xor_sync(0xffffffffu, saB[j], 2);
            }
            if (t4 == 0) {
#pragma unroll
                for (int j = 0; j < DACT; j++) {
                    atomicAdd(&sp[rA*DACT + j], saA[j]);
                    atomicAdd(&sp[rB*DACT + j], saB[j]);
                }
            }
        }
        __syncthreads();
        float* sout = soutB + (size_t)net*ROWS*DACT;
        for (int i = tid; i < MTI*DACT; i += 256)
            sout[(size_t)M0*DACT + i] = sp[i];
    }
}

// ---------------- SVGD step (one block per batch) ---------------------------
__global__ void svgd_kernel(float* __restrict__ a, float* __restrict__ lp,
                            const float* __restrict__ s1, const float* __restrict__ s2,
                            const float* __restrict__ q1, const float* __restrict__ q2) {
    __shared__ float Xs[NPART][DACT];
    __shared__ float Ss[NPART][DACT];
    __shared__ float dsq[NPART][NPART];
    __shared__ float sbuf[512];
    __shared__ float Km[NPART][NPART];
    __shared__ float t1s[NPART];
    __shared__ float g_sh;
    const int b = blockIdx.x, tid = threadIdx.x; // 256 threads

    if (tid < NPART*DACT) {
        int i = tid / DACT, d = tid % DACT;
        int r = b*NPART + i;
        Xs[i][d] = a[r*DACT + d];
        float qa = q1[r], qb = q2[r];
        float sv;
        if (qa < qb)      sv = s1[r*DACT + d];
        else if (qb < qa) sv = s2[r*DACT + d];
        else              sv = 0.5f * (s1[r*DACT + d] + s2[r*DACT + d]);
        Ss[i][d] = sv;
    }
    __syncthreads();
    for (int t = tid; t < NPART*NPART; t += 256) {
        int i = t >> 5, j = t & 31;
        float acc = 0.f;
#pragma unroll
        for (int d = 0; d < DACT; d++) { float df = Xs[i][d] - Xs[j][d]; acc += df*df; }
        dsq[i][j] = acc;
        if (i < j) {
            int rank = i*31 - (i*(i-1))/2 + (j - i - 1);
            sbuf[rank] = acc;
        }
    }
    if (tid < 16) sbuf[496 + tid] = 3.0e38f;
    for (int k = 2; k <= 512; k <<= 1)
        for (int j = k >> 1; j > 0; j >>= 1) {
            __syncthreads();
            for (int t = tid; t < 512; t += 256) {
                int ixj = t ^ j;
                if (ixj > t) {
                    float x = sbuf[t], y = sbuf[ixj];
                    bool up = ((t & k) == 0);
                    if ((x > y) == up) { sbuf[t] = y; sbuf[ixj] = x; }
                }
            }
        }
    __syncthreads();
    if (tid == 0) {
        float med = 0.5f * (sbuf[239] + sbuf[240]);
        float h = med / logf((float)NPART + 1.0f);
        g_sh = 1.0f / (2.0f * h + 1e-8f);
    }
    __syncthreads();
    float g = g_sh;
    for (int t = tid; t < NPART*NPART; t += 256) {
        int i = t >> 5, j = t & 31;
        Km[i][j] = expf(-g * dsq[i][j]);
    }
    __syncthreads();
    if (tid < NPART*DACT) {
        int i = tid / DACT, d = tid % DACT;
        float xi = Xs[i][d];
        float acc = 0.f, accg = 0.f;
#pragma unroll
        for (int j = 0; j < NPART; j++) {
            float kij = Km[i][j];
            acc  += kij * Ss[j][d];
            accg += kij * (xi - Xs[j][d]);
        }
        float phi = (acc + 2.f * g * accg) * (1.0f / (float)NPART);
        a[(b*NPART + i)*DACT + d] += LRC * phi;
    }
    if (tid < NPART) {
        int i = tid;
        float t1 = 0.f;
        for (int j = 0; j < NPART; j++) {
            float kij = Km[i][j];
            float dd = 0.f;
#pragma unroll
            for (int d = 0; d < DACT; d++) dd += (Xs[i][d] - Xs[j][d]) * Ss[j][d];
            t1 += kij * dd;
        }
        t1s[i] = (-2.f * g / (float)(NPART - 1)) * t1;
    }
    __syncthreads();
    if (tid < NPART) {
        int j = tid;
        float t2 = 0.f;
        for (int i = 0; i < NPART; i++) {
            float kij = Km[i][j];
            float inner = 2.f * g * dsq[i][j] * kij
                        - (float)DACT * (kij - (i == j ? 1.f : 0.f));
            t2 += inner;
        }
        t2 *= (-2.f * g / (float)(NPART - 1));
        lp[b*NPART + j] -= LRC * (t1s[j] + t2);
    }
}

// ---------------- finalize --------------------------------------------------
__global__ void tanh_kernel(const float* __restrict__ a, float* __restrict__ out) {
    int idx = blockIdx.x * blockDim.x + threadIdx.x;
    if (idx < A_TOTAL) out[idx] = tanhf(a[idx]);
}

__global__ void logpa_kernel(const float* __restrict__ a, const float* __restrict__ a0,
                             const float* __restrict__ lp, float* __restrict__ out) {
    int b = blockIdx.x;
    int i = threadIdx.x; // 32
    int r = b*NPART + i;
    float s0 = 0.f, lt = 0.f;
#pragma unroll
    for (int d = 0; d < DACT; d++) {
        float v0 = a0[r*DACT + d]; s0 += v0*v0;
        float av = a[r*DACT + d];
        float z = -2.f * av;
        float sp = fmaxf(z, 0.f) + log1pf(expf(-fabsf(z)));
        lt -= 2.f * (0.6931471805599453f - av - sp);
    }
    float ln = -(float)DACT * 0.5f * logf(2.f * 3.14159265358979f * 0.3f)
             - (0.5f / 0.3f) * s0;
    float v = ln + lp[r] + lt;
#pragma unroll
    for (int o = 16; o; o >>= 1) v += __shfl_xor_sync(0xffffffffu, v, o);
    if (i == 0) out[A_TOTAL + b] = v * (1.0f / (float)NPART);
}

// ---------------- host ------------------------------------------------------
extern "C" void kernel_launch(void* const* d_in, const int* in_sizes, int n_in,
                              void* d_out, int out_size) {
    const float* obs = (const float*)d_in[0];
    const float* a0  = (const float*)d_in[1];
    const float* W1[2] = {(const float*)d_in[2],  (const float*)d_in[8]};
    const float* b1[2] = {(const float*)d_in[3],  (const float*)d_in[9]};
    const float* W2[2] = {(const float*)d_in[4],  (const float*)d_in[10]};
    const float* b2[2] = {(const float*)d_in[5],  (const float*)d_in[11]};
    const float* W3[2] = {(const float*)d_in[6],  (const float*)d_in[12]};
    const float* b3[2] = {(const float*)d_in[7],  (const float*)d_in[13]};
    float* out = (float*)d_out;

    float *aprojB, *qB, *sB, *aB, *lpB;
    __nv_bfloat16 *w2hB, *w2lB, *w2thB, *w2tlB, *w3hB, *w3lB;
    cudaGetSymbolAddress((void**)&aprojB, d_aproj);
    cudaGetSymbolAddress((void**)&w2hB,   d_w2h);
    cudaGetSymbolAddress((void**)&w2lB,   d_w2l);
    cudaGetSymbolAddress((void**)&w2thB,  d_w2th);
    cudaGetSymbolAddress((void**)&w2tlB,  d_w2tl);
    cudaGetSymbolAddress((void**)&w3hB,   d_w3h);
    cudaGetSymbolAddress((void**)&w3lB,   d_w3l);
    cudaGetSymbolAddress((void**)&qB,     d_qv);
    cudaGetSymbolAddress((void**)&sB,     d_sv);
    cudaGetSymbolAddress((void**)&aB,     d_av);
    cudaGetSymbolAddress((void**)&lpB,    d_lp);

    static int attr_done = 0;
    if (!attr_done) {
        cudaFuncSetAttribute(gemm_step_mma, cudaFuncAttributeMaxDynamicSharedMemorySize, SMEM_TOTAL);
        attr_done = 1;
    }

    init_kernel<<<(A_TOTAL + 255)/256, 256>>>(a0, aB, lpB);
    prep_kernel<<<512, 256>>>(W2[0], W2[1], W3[0], W3[1]);
    obsproj_kernel<<<2*ROWS/32, 256>>>(obs, W1[0], W1[1], b1[0], b1[1], aprojB);

    for (int step = 0; step < NSTEPS; step++) {
        gemm_step_mma<<<2*TILES, 256, SMEM_TOTAL>>>(
            aprojB, aB, W1[0], W1[1],
            w2thB, w2tlB, w2hB, w2lB,
            b2[0], b2[1], W3[0], W3[1], b3[0], b3[1],
            w3hB, w3lB,
            qB, sB);
        svgd_kernel<<<BATCH, 256>>>(aB, lpB, sB, sB + (size_t)ROWS*DACT,
                                    qB, qB + ROWS);
    }
    tanh_kernel<<<(A_TOTAL + 255)/256, 256>>>(aB, out);
    logpa_kernel<<<BATCH, 32>>>(aB, a0, lpB, out);
}